// round 1
// baseline (speedup 1.0000x reference)
#include <cuda_runtime.h>

#define NN 8192
#define DD 512

// deterministic scratch (no atomics anywhere)
__device__ float g_b[DD];
__device__ float g_s2[NN];
__device__ float g_w[NN];
__device__ float g_part[128 * DD];
__device__ float g_u[DD];
__device__ float g_vpart[32 * DD];
__device__ float g_v[DD];

// K1: b[k] = sum_o W[k,o] * a2[o]    (a2 = attention_vector[512:1024])
// grid 16 x 128 threads (4 warps/block), warp-per-row, coalesced float4 reads
__global__ void k_b(const float* __restrict__ W, const float* __restrict__ att) {
    const float4* W4 = (const float4*)W;
    const float4* a4 = (const float4*)(att + DD);
    int warp = threadIdx.x >> 5, lane = threadIdx.x & 31;
    int gw = blockIdx.x * 4 + warp;          // 0..63
    for (int r = 0; r < 8; r++) {
        int k = gw * 8 + r;
        float acc = 0.f;
#pragma unroll
        for (int j = 0; j < 4; j++) {
            float4 w4 = W4[k * 128 + lane + 32 * j];
            float4 b4 = a4[lane + 32 * j];
            acc += w4.x * b4.x + w4.y * b4.y + w4.z * b4.z + w4.w * b4.w;
        }
#pragma unroll
        for (int o = 16; o > 0; o >>= 1) acc += __shfl_down_sync(~0u, acc, o);
        if (lane == 0) g_b[k] = acc;
    }
}

// K2: s2[i] = dot(X[i,:], b)   warp-per-row, b staged in shared
__global__ void k_s2(const float* __restrict__ X) {
    __shared__ float4 sb[128];
    int t = threadIdx.x;
    if (t < 128) sb[t] = ((const float4*)g_b)[t];
    __syncthreads();
    int warp = t >> 5, lane = t & 31;
    int i = blockIdx.x * 8 + warp;
    const float4* X4 = (const float4*)X;
    float acc = 0.f;
#pragma unroll
    for (int j = 0; j < 4; j++) {
        float4 x4 = X4[(size_t)i * 128 + lane + 32 * j];
        float4 b4 = sb[lane + 32 * j];
        acc += x4.x * b4.x + x4.y * b4.y + x4.z * b4.z + x4.w * b4.w;
    }
#pragma unroll
    for (int o = 16; o > 0; o >>= 1) acc += __shfl_down_sync(~0u, acc, o);
    if (lane == 0) g_s2[i] = acc;
}

// K3: w = softmax(s2) over all 8192 elements, one block of 1024 threads
__global__ void k_softmax() {
    int t = threadIdx.x;
    float vals[8];
    float m = -1e30f;
#pragma unroll
    for (int j = 0; j < 8; j++) {
        vals[j] = g_s2[t + 1024 * j];
        m = fmaxf(m, vals[j]);
    }
    __shared__ float redm[32], reds[32];
#pragma unroll
    for (int o = 16; o > 0; o >>= 1) m = fmaxf(m, __shfl_xor_sync(~0u, m, o));
    if ((t & 31) == 0) redm[t >> 5] = m;
    __syncthreads();
    if (t < 32) {
        float x = redm[t];
#pragma unroll
        for (int o = 16; o > 0; o >>= 1) x = fmaxf(x, __shfl_xor_sync(~0u, x, o));
        redm[t] = x;
    }
    __syncthreads();
    float bm = redm[0];
    float s = 0.f;
#pragma unroll
    for (int j = 0; j < 8; j++) {
        vals[j] = expf(vals[j] - bm);
        s += vals[j];
    }
#pragma unroll
    for (int o = 16; o > 0; o >>= 1) s += __shfl_xor_sync(~0u, s, o);
    if ((t & 31) == 0) reds[t >> 5] = s;
    __syncthreads();
    if (t < 32) {
        float x = reds[t];
#pragma unroll
        for (int o = 16; o > 0; o >>= 1) x += __shfl_xor_sync(~0u, x, o);
        reds[t] = x;
    }
    __syncthreads();
    float inv = 1.f / reds[0];
#pragma unroll
    for (int j = 0; j < 8; j++) g_w[t + 1024 * j] = vals[j] * inv;
}

// K4: per-block partial of u = w^T X. 128 blocks x 512 threads; block b owns rows [b*64, b*64+64)
__global__ void k_part(const float* __restrict__ X) {
    __shared__ float sw[64];
    int t = threadIdx.x, b = blockIdx.x;
    if (t < 64) sw[t] = g_w[b * 64 + t];
    __syncthreads();
    float acc = 0.f;
    const float* Xb = X + (size_t)b * 64 * DD + t;
#pragma unroll 4
    for (int r = 0; r < 64; r++) acc += sw[r] * Xb[(size_t)r * DD];
    g_part[b * DD + t] = acc;
}

// K5: u[c] = sum_b part[b][c]  (deterministic tree-free reduce, coalesced)
__global__ void k_u() {
    int t = threadIdx.x;
    float acc = 0.f;
#pragma unroll 8
    for (int b = 0; b < 128; b++) acc += g_part[b * DD + t];
    g_u[t] = acc;
}

// K6: vpart[b][o] = sum_{k in block-b's 16 rows} u[k] * W[k,o]
__global__ void k_vpart(const float* __restrict__ W) {
    __shared__ float su[16];
    int t = threadIdx.x, b = blockIdx.x;
    if (t < 16) su[t] = g_u[b * 16 + t];
    __syncthreads();
    float acc = 0.f;
#pragma unroll
    for (int k = 0; k < 16; k++) acc += su[k] * W[(size_t)(b * 16 + k) * DD + t];
    g_vpart[b * DD + t] = acc;
}

// K7: v[o] = sum_b vpart[b][o]
__global__ void k_v() {
    int t = threadIdx.x;
    float acc = 0.f;
#pragma unroll
    for (int b = 0; b < 32; b++) acc += g_vpart[b * DD + t];
    g_v[t] = acc;
}

// K8: out[i,:] = v for all i. Pure float4 streaming store.
// blockDim=256 (multiple of 128) so (global_j & 127) == (t & 127): one shared read per thread.
__global__ void k_bcast(float4* __restrict__ out) {
    __shared__ float4 sv[128];
    int t = threadIdx.x;
    if (t < 128) sv[t] = ((const float4*)g_v)[t];
    __syncthreads();
    float4 val = sv[t & 127];
    size_t total = (size_t)NN * DD / 4;  // 1,048,576 float4
    size_t stride = (size_t)gridDim.x * blockDim.x;
    for (size_t j = (size_t)blockIdx.x * blockDim.x + t; j < total; j += stride)
        out[j] = val;
}

extern "C" void kernel_launch(void* const* d_in, const int* in_sizes, int n_in,
                              void* d_out, int out_size) {
    const float* X   = (const float*)d_in[0];  // node_features  [8192, 512]
    const float* W   = (const float*)d_in[1];  // weight_matrix  [512, 512]
    const float* att = (const float*)d_in[2];  // attention_vector [1024, 1]
    float* out = (float*)d_out;                // [8192, 512] fp32

    k_b<<<16, 128>>>(W, att);
    k_s2<<<1024, 256>>>(X);
    k_softmax<<<1, 1024>>>();
    k_part<<<128, 512>>>(X);
    k_u<<<1, 512>>>();
    k_vpart<<<32, 512>>>(W);
    k_v<<<1, 512>>>();
    k_bcast<<<2048, 256>>>((float4*)out);
}

// round 2
// speedup vs baseline: 1.2868x; 1.2868x over previous
#include <cuda_runtime.h>

#define NN 8192
#define DD 512

// deterministic scratch (no atomics anywhere)
__device__ float g_b[DD];
__device__ float g_s2[NN];
__device__ float g_w[NN];
__device__ float g_part[128 * DD];
__device__ float g_vpart[32 * DD];
__device__ float g_v[DD];

// K1: b[k] = sum_o W[k,o] * a2[o]    (a2 = attention_vector[512:1024])
__global__ void k_b(const float* __restrict__ W, const float* __restrict__ att) {
    const float4* W4 = (const float4*)W;
    const float4* a4 = (const float4*)(att + DD);
    int warp = threadIdx.x >> 5, lane = threadIdx.x & 31;
    int gw = blockIdx.x * 4 + warp;          // 0..63
    for (int r = 0; r < 8; r++) {
        int k = gw * 8 + r;
        float acc = 0.f;
#pragma unroll
        for (int j = 0; j < 4; j++) {
            float4 w4 = W4[k * 128 + lane + 32 * j];
            float4 b4 = a4[lane + 32 * j];
            acc += w4.x * b4.x + w4.y * b4.y + w4.z * b4.z + w4.w * b4.w;
        }
#pragma unroll
        for (int o = 16; o > 0; o >>= 1) acc += __shfl_down_sync(~0u, acc, o);
        if (lane == 0) g_b[k] = acc;
    }
}

// K2: s2[i] = dot(X[i,:], b)   warp-per-row, b staged in shared (first DRAM pass over X)
__global__ void k_s2(const float* __restrict__ X) {
    __shared__ float4 sb[128];
    int t = threadIdx.x;
    if (t < 128) sb[t] = ((const float4*)g_b)[t];
    __syncthreads();
    int warp = t >> 5, lane = t & 31;
    int i = blockIdx.x * 8 + warp;
    const float4* X4 = (const float4*)X;
    float acc = 0.f;
#pragma unroll
    for (int j = 0; j < 4; j++) {
        float4 x4 = X4[(size_t)i * 128 + lane + 32 * j];
        float4 b4 = sb[lane + 32 * j];
        acc += x4.x * b4.x + x4.y * b4.y + x4.z * b4.z + x4.w * b4.w;
    }
#pragma unroll
    for (int o = 16; o > 0; o >>= 1) acc += __shfl_down_sync(~0u, acc, o);
    if (lane == 0) g_s2[i] = acc;
}

// K3: w = softmax(s2) over all 8192 elements, one block of 1024 threads
__global__ void k_softmax() {
    int t = threadIdx.x;
    float vals[8];
    float m = -1e30f;
#pragma unroll
    for (int j = 0; j < 8; j++) {
        vals[j] = g_s2[t + 1024 * j];
        m = fmaxf(m, vals[j]);
    }
    __shared__ float redm[32], reds[32];
#pragma unroll
    for (int o = 16; o > 0; o >>= 1) m = fmaxf(m, __shfl_xor_sync(~0u, m, o));
    if ((t & 31) == 0) redm[t >> 5] = m;
    __syncthreads();
    if (t < 32) {
        float x = redm[t];
#pragma unroll
        for (int o = 16; o > 0; o >>= 1) x = fmaxf(x, __shfl_xor_sync(~0u, x, o));
        redm[t] = x;
    }
    __syncthreads();
    float bm = redm[0];
    float s = 0.f;
#pragma unroll
    for (int j = 0; j < 8; j++) {
        vals[j] = expf(vals[j] - bm);
        s += vals[j];
    }
#pragma unroll
    for (int o = 16; o > 0; o >>= 1) s += __shfl_xor_sync(~0u, s, o);
    if ((t & 31) == 0) reds[t >> 5] = s;
    __syncthreads();
    if (t < 32) {
        float x = reds[t];
#pragma unroll
        for (int o = 16; o > 0; o >>= 1) x += __shfl_xor_sync(~0u, x, o);
        reds[t] = x;
    }
    __syncthreads();
    float inv = 1.f / reds[0];
#pragma unroll
    for (int j = 0; j < 8; j++) g_w[t + 1024 * j] = vals[j] * inv;
}

// K4: per-block partial of u = w^T X, vectorized with high MLP.
// 128 blocks x 512 threads. Block b owns rows [b*64, b*64+64).
// Thread t: sub = t>>7 (0..3) picks a 16-row group, c = t&127 picks a float4 column.
// 16 fully-unrolled independent float4 loads per thread (MLP~16), 2 accumulators.
// X is L2-resident after k_s2's pass -> this should run at L2 bandwidth.
__global__ void k_part(const float4* __restrict__ X4) {
    __shared__ float sw[64];
    __shared__ float4 red[4][128];   // 8 KB
    int t = threadIdx.x, b = blockIdx.x;
    if (t < 64) sw[t] = g_w[b * 64 + t];
    __syncthreads();
    int sub = t >> 7, c = t & 127;
    const float4* Xb = X4 + ((size_t)(b * 64 + sub * 16)) * 128 + c;
    float4 a0 = {0.f, 0.f, 0.f, 0.f}, a1 = a0;
#pragma unroll
    for (int r = 0; r < 16; r += 2) {
        float4 x0 = Xb[(size_t)r * 128];
        float4 x1 = Xb[(size_t)(r + 1) * 128];
        float w0 = sw[sub * 16 + r];
        float w1 = sw[sub * 16 + r + 1];
        a0.x += w0 * x0.x; a0.y += w0 * x0.y; a0.z += w0 * x0.z; a0.w += w0 * x0.w;
        a1.x += w1 * x1.x; a1.y += w1 * x1.y; a1.z += w1 * x1.z; a1.w += w1 * x1.w;
    }
    a0.x += a1.x; a0.y += a1.y; a0.z += a1.z; a0.w += a1.w;
    red[sub][c] = a0;
    __syncthreads();
    if (t < 128) {
        float4 r0 = red[0][t], r1 = red[1][t], r2 = red[2][t], r3 = red[3][t];
        float4 s;
        s.x = (r0.x + r1.x) + (r2.x + r3.x);
        s.y = (r0.y + r1.y) + (r2.y + r3.y);
        s.z = (r0.z + r1.z) + (r2.z + r3.z);
        s.w = (r0.w + r1.w) + (r2.w + r3.w);
        ((float4*)g_part)[b * 128 + t] = s;
    }
}

// K5 (fused u-reduce + v-partial): 32 blocks x 512 threads.
// Phase A: warp w (0..15) reduces u[b*16+w] = sum_p g_part[p*512 + b*16 + w].
// Phase B: vpart[b][o] = sum_{k in 16 rows} u[k] * W[k,o].
__global__ void k_uv(const float* __restrict__ W) {
    __shared__ float su[16];
    int t = threadIdx.x, b = blockIdx.x;
    int warp = t >> 5, lane = t & 31;
    int k = b * 16 + warp;
    float acc = 0.f;
#pragma unroll
    for (int p = 0; p < 4; p++) acc += g_part[(lane + 32 * p) * DD + k];
#pragma unroll
    for (int o = 16; o > 0; o >>= 1) acc += __shfl_down_sync(~0u, acc, o);
    if (lane == 0) su[warp] = acc;
    __syncthreads();
    float vacc = 0.f;
#pragma unroll
    for (int r = 0; r < 16; r++) vacc += su[r] * W[(size_t)(b * 16 + r) * DD + t];
    g_vpart[b * DD + t] = vacc;
}

// K6: v[o] = sum_b vpart[b][o]
__global__ void k_v() {
    int t = threadIdx.x;
    float acc = 0.f;
#pragma unroll
    for (int b = 0; b < 32; b++) acc += g_vpart[b * DD + t];
    g_v[t] = acc;
}

// K7: out[i,:] = v for all i. Pure float4 streaming store.
__global__ void k_bcast(float4* __restrict__ out) {
    __shared__ float4 sv[128];
    int t = threadIdx.x;
    if (t < 128) sv[t] = ((const float4*)g_v)[t];
    __syncthreads();
    float4 val = sv[t & 127];
    size_t total = (size_t)NN * DD / 4;  // 1,048,576 float4
    size_t stride = (size_t)gridDim.x * blockDim.x;
    for (size_t j = (size_t)blockIdx.x * blockDim.x + t; j < total; j += stride)
        out[j] = val;
}

extern "C" void kernel_launch(void* const* d_in, const int* in_sizes, int n_in,
                              void* d_out, int out_size) {
    const float* X   = (const float*)d_in[0];  // node_features  [8192, 512]
    const float* W   = (const float*)d_in[1];  // weight_matrix  [512, 512]
    const float* att = (const float*)d_in[2];  // attention_vector [1024, 1]
    float* out = (float*)d_out;                // [8192, 512] fp32

    k_b<<<16, 128>>>(W, att);
    k_s2<<<1024, 256>>>(X);
    k_softmax<<<1, 1024>>>();
    k_part<<<128, 512>>>((const float4*)X);
    k_uv<<<32, 512>>>(W);
    k_v<<<1, 512>>>();
    k_bcast<<<2048, 256>>>((float4*)out);
}

// round 3
// speedup vs baseline: 1.5466x; 1.2019x over previous
#include <cuda_runtime.h>

#define NN 8192
#define DD 512
#define NB 256          // k_fused blocks (32 rows each)

// deterministic scratch (no atomics anywhere)
__device__ float g_b[DD];
__device__ float g_pm[NB];            // per-block running max
__device__ float g_pe[NB];            // per-block exp-sum (scaled by exp(-m_b))
__device__ float g_pp[NB * DD];       // per-block weighted row-sum partials
__device__ float g_vpart[32 * DD];
__device__ float g_v[DD];

// K1: b[k] = sum_o W[k,o] * a2[o]    (a2 = attention_vector[512:1024])
__global__ void k_b(const float* __restrict__ W, const float* __restrict__ att) {
    const float4* W4 = (const float4*)W;
    const float4* a4 = (const float4*)(att + DD);
    int warp = threadIdx.x >> 5, lane = threadIdx.x & 31;
    int gw = blockIdx.x * 4 + warp;          // 0..63
    for (int r = 0; r < 8; r++) {
        int k = gw * 8 + r;
        float acc = 0.f;
#pragma unroll
        for (int j = 0; j < 4; j++) {
            float4 w4 = W4[k * 128 + lane + 32 * j];
            float4 b4 = a4[lane + 32 * j];
            acc += w4.x * b4.x + w4.y * b4.y + w4.z * b4.z + w4.w * b4.w;
        }
#pragma unroll
        for (int o = 16; o > 0; o >>= 1) acc += __shfl_down_sync(~0u, acc, o);
        if (lane == 0) g_b[k] = acc;
    }
}

// K2: single pass over X with online softmax accumulation.
// 256 blocks x 256 threads (8 warps). Block b owns rows [b*32, b*32+32);
// warp w owns 4 consecutive rows. Lane l covers float4 slots {l+32q}.
// Per row: load 4 float4 (coalesced), dot with b, warp-reduce to s,
// then online-softmax update of (m, e, acc[4]) using the SAME registers.
__global__ void k_fused(const float4* __restrict__ X4) {
    __shared__ float4 sb[128];
    __shared__ float sm_m[8], sm_e[8];
    __shared__ float4 sm_p[8][128];      // 16 KB
    int t = threadIdx.x, b = blockIdx.x;
    int w = t >> 5, l = t & 31;
    if (t < 128) sb[t] = ((const float4*)g_b)[t];
    __syncthreads();

    float m = -1e30f, e = 0.f;
    float4 acc[4];
#pragma unroll
    for (int q = 0; q < 4; q++) acc[q] = make_float4(0.f, 0.f, 0.f, 0.f);

    int row0 = b * 32 + w * 4;
#pragma unroll
    for (int i = 0; i < 4; i++) {
        size_t base = (size_t)(row0 + i) * 128;
        float4 x[4];
#pragma unroll
        for (int q = 0; q < 4; q++) x[q] = X4[base + l + 32 * q];
        float d = 0.f;
#pragma unroll
        for (int q = 0; q < 4; q++) {
            float4 bq = sb[l + 32 * q];
            d += x[q].x * bq.x + x[q].y * bq.y + x[q].z * bq.z + x[q].w * bq.w;
        }
#pragma unroll
        for (int o = 16; o > 0; o >>= 1) d += __shfl_xor_sync(~0u, d, o);
        float mn = fmaxf(m, d);
        float cold = expf(m - mn);       // first iter: exp(-huge)=0
        float cs = expf(d - mn);
        e = e * cold + cs;
#pragma unroll
        for (int q = 0; q < 4; q++) {
            acc[q].x = acc[q].x * cold + cs * x[q].x;
            acc[q].y = acc[q].y * cold + cs * x[q].y;
            acc[q].z = acc[q].z * cold + cs * x[q].z;
            acc[q].w = acc[q].w * cold + cs * x[q].w;
        }
        m = mn;
    }
    // warp -> smem (all lanes hold identical m, e)
#pragma unroll
    for (int q = 0; q < 4; q++) sm_p[w][l + 32 * q] = acc[q];
    if (l == 0) { sm_m[w] = m; sm_e[w] = e; }
    __syncthreads();

    // block combine
    float mb = sm_m[0];
#pragma unroll
    for (int q = 1; q < 8; q++) mb = fmaxf(mb, sm_m[q]);
    if (t < 128) {
        float4 s = make_float4(0.f, 0.f, 0.f, 0.f);
#pragma unroll
        for (int q = 0; q < 8; q++) {
            float sc = expf(sm_m[q] - mb);
            float4 p = sm_p[q][t];
            s.x += sc * p.x; s.y += sc * p.y; s.z += sc * p.z; s.w += sc * p.w;
        }
        ((float4*)(g_pp + b * DD))[t] = s;
    }
    if (t == 0) {
        float eb = 0.f;
#pragma unroll
        for (int q = 0; q < 8; q++) eb += expf(sm_m[q] - mb) * sm_e[q];
        g_pm[b] = mb;
        g_pe[b] = eb;
    }
}

// K3: combine the 256 partials into u (for this block's 16 k-rows), then
// vpart[j][o] = (1/S) * sum_k u[k] W[k,o].  32 blocks x 512 threads.
// The 256 exp-scales are computed ONCE into smem (1 exp per thread), not per-use.
__global__ void k_uv(const float* __restrict__ W) {
    __shared__ float spm[NB], sesc[NB];
    __shared__ float su[16];
    __shared__ float sS;
    int t = threadIdx.x, j = blockIdx.x;
    int w = t >> 5, l = t & 31;

    if (t < NB) spm[t] = g_pm[t];
    __syncthreads();
    // warp 0: global max
    if (w == 0) {
        float gm = -1e30f;
#pragma unroll
        for (int q = 0; q < 8; q++) gm = fmaxf(gm, spm[l + 32 * q]);
#pragma unroll
        for (int o = 16; o > 0; o >>= 1) gm = fmaxf(gm, __shfl_xor_sync(~0u, gm, o));
        if (l == 0) sS = gm;   // temporarily holds gm
    }
    __syncthreads();
    float gm = sS;
    if (t < NB) sesc[t] = expf(spm[t] - gm);
    __syncthreads();
    // warp 0: S = sum esc[p]*e[p]
    if (w == 0) {
        float s = 0.f;
#pragma unroll
        for (int q = 0; q < 8; q++) {
            int p = l + 32 * q;
            s += sesc[p] * g_pe[p];
        }
#pragma unroll
        for (int o = 16; o > 0; o >>= 1) s += __shfl_xor_sync(~0u, s, o);
        if (l == 0) sS = s;
    }
    // u[k] for this block's 16 rows: warp w (w<16) handles k=j*16+w
    if (w < 16) {
        int k = j * 16 + w;
        float acc = 0.f;
#pragma unroll
        for (int q = 0; q < 8; q++) {
            int p = l + 32 * q;
            acc += sesc[p] * g_pp[p * DD + k];
        }
#pragma unroll
        for (int o = 16; o > 0; o >>= 1) acc += __shfl_down_sync(~0u, acc, o);
        if (l == 0) su[w] = acc;
    }
    __syncthreads();
    float inv = 1.f / sS;
    float vacc = 0.f;
#pragma unroll
    for (int r = 0; r < 16; r++) vacc += su[r] * W[(size_t)(j * 16 + r) * DD + t];
    g_vpart[j * DD + t] = vacc * inv;
}

// K4: v[o] = sum_j vpart[j][o]
__global__ void k_v() {
    int t = threadIdx.x;
    float acc = 0.f;
#pragma unroll
    for (int j = 0; j < 32; j++) acc += g_vpart[j * DD + t];
    g_v[t] = acc;
}

// K5: out[i,:] = v for all i. Pure float4 streaming store.
__global__ void k_bcast(float4* __restrict__ out) {
    __shared__ float4 sv[128];
    int t = threadIdx.x;
    if (t < 128) sv[t] = ((const float4*)g_v)[t];
    __syncthreads();
    float4 val = sv[t & 127];
    size_t total = (size_t)NN * DD / 4;  // 1,048,576 float4
    size_t stride = (size_t)gridDim.x * blockDim.x;
    for (size_t j = (size_t)blockIdx.x * blockDim.x + t; j < total; j += stride)
        out[j] = val;
}

extern "C" void kernel_launch(void* const* d_in, const int* in_sizes, int n_in,
                              void* d_out, int out_size) {
    const float* X   = (const float*)d_in[0];  // node_features  [8192, 512]
    const float* W   = (const float*)d_in[1];  // weight_matrix  [512, 512]
    const float* att = (const float*)d_in[2];  // attention_vector [1024, 1]
    float* out = (float*)d_out;                // [8192, 512] fp32

    k_b<<<16, 128>>>(W, att);
    k_fused<<<NB, 256>>>((const float4*)X);
    k_uv<<<32, 512>>>(W);
    k_v<<<1, 512>>>();
    k_bcast<<<2048, 256>>>((float4*)out);
}